// round 9
// baseline (speedup 1.0000x reference)
#include <cuda_runtime.h>

#define H 8192
#define W 8192
#define KH 7
#define KW 7
#define OH (H - KH + 1)   // 8186
#define OW (W - KW + 1)   // 8186

#define TPB    128
#define RPT    12                    // rows per thread
#define TILE_X 64                    // 32 lanes * 2 cols
#define TILE_Y 48                    // 4 warps * 12 rows
#define SM_H   (TILE_Y + KH - 1)     // 54
#define SM_W   (TILE_X + KW - 1)     // 70
#define SP     72                    // smem pitch (floats)
#define VLEN   (RPT + KH - 1)        // 18

typedef unsigned long long u64;

__device__ __forceinline__ u64 fma2(u64 a, u64 b, u64 c) {
    u64 d;
    asm("fma.rn.f32x2 %0, %1, %2, %3;" : "=l"(d) : "l"(a), "l"(b), "l"(c));
    return d;
}
__device__ __forceinline__ u64 splat2(float w) {
    u64 d;
    asm("mov.b64 %0, {%1, %1};" : "=l"(d) : "f"(w));
    return d;
}
// {hi(a), lo(b)} — register MOVs only
__device__ __forceinline__ u64 crossing(u64 a, u64 b) {
    u64 r;
    asm("{\n\t.reg .b32 al, ah, bl, bh;\n\t"
        "mov.b64 {al, ah}, %1;\n\t"
        "mov.b64 {bl, bh}, %2;\n\t"
        "mov.b64 %0, {ah, bl};\n\t}"
        : "=l"(r) : "l"(a), "l"(b));
    return r;
}

__global__ __launch_bounds__(TPB)
void conv7x7_ev_kernel(const float* __restrict__ x,
                       const float* __restrict__ wgt,
                       const float* __restrict__ bias,
                       float* __restrict__ out)
{
    __shared__ __align__(16) float tile[SM_H * SP];
    __shared__ __align__(16) u64 wpair[56];   // [kc*7 + kr], pre-splatted {w,w}

    const int tid  = threadIdx.x;
    const int col0 = blockIdx.x * TILE_X;
    const int row0 = blockIdx.y * TILE_Y;

    // Weight pair table: wpair[kc*7+kr] = {w,w} for wgt[kr*7+kc]
    if (tid < KH * KW) {
        const int kc = tid / 7;
        const int kr = tid - kc * 7;
        wpair[tid] = splat2(wgt[kr * KW + kc]);
    }

    // ---- Tile fill: single copy, clamped ----
    if (row0 + SM_H <= H && col0 + SM_W <= W) {
        for (int idx = tid; idx < SM_H * 35; idx += TPB) {
            const int r  = idx / 35;
            const int c2 = idx - r * 35;
            const float2 v = __ldg((const float2*)&x[(size_t)(row0 + r) * W + col0 + 2 * c2]);
            *(float2*)&tile[r * SP + 2 * c2] = v;
        }
    } else {
        for (int idx = tid; idx < SM_H * SM_W; idx += TPB) {
            const int r = idx / SM_W;
            const int c = idx - r * SM_W;
            const int gr = min(row0 + r, H - 1);
            const int gc = min(col0 + c, W - 1);
            tile[r * SP + c] = __ldg(&x[(size_t)gr * W + gc]);
        }
    }
    __syncthreads();

    const int lane  = tid & 31;
    const int rbase = (tid >> 5) * RPT;       // 0,12,24,36
    const int cb    = lane * 2;               // 0..62 (u64-aligned)

    u64 acc[RPT];
#pragma unroll
    for (int o = 0; o < RPT; o++) acc[o] = 0ULL;

    const float* base = &tile[rbase * SP + cb];

    // ---- Step 0: kc = 0 (aligned window, kept for crossings) ----
    u64 Wc[VLEN];
    {
        u64 w0[KH];
#pragma unroll
        for (int kr = 0; kr < KH; kr++) w0[kr] = wpair[kr];   // kc=0
#pragma unroll
        for (int t = 0; t < VLEN; t++) {
            const u64 Wn = *(const u64*)(base + t * SP);
            Wc[t] = Wn;
#pragma unroll
            for (int kr = 0; kr < KH; kr++) {
                const int o = t - kr;
                if (o >= 0 && o < RPT) acc[o] = fma2(Wn, w0[kr], acc[o]);
            }
        }
    }

    // ---- Steps s=1..3: load even window kc=2s, odd kc=2s-1 via crossing ----
#pragma unroll
    for (int s = 1; s <= 3; s++) {
        u64 we[KH], wo[KH];
#pragma unroll
        for (int kr = 0; kr < KH; kr++) {
            we[kr] = wpair[(2 * s) * 7 + kr];
            wo[kr] = wpair[(2 * s - 1) * 7 + kr];
        }
#pragma unroll
        for (int t = 0; t < VLEN; t++) {
            const u64 Wn = *(const u64*)(base + t * SP + 2 * s);
            const u64 X  = crossing(Wc[t], Wn);   // cols {2s-1, 2s}
            Wc[t] = Wn;
#pragma unroll
            for (int kr = 0; kr < KH; kr++) {
                const int o = t - kr;
                if (o >= 0 && o < RPT) {
                    u64 a = acc[o];
                    a = fma2(X,  wo[kr], a);
                    a = fma2(Wn, we[kr], a);
                    acc[o] = a;
                }
            }
        }
    }

    // ---- Epilogue: bias + STG.64 (OW even: pairs never straddle) ----
    const u64 b2 = splat2(__ldg(&bias[0]));
    const int ocol = col0 + cb;
    if (ocol < OW) {
#pragma unroll
        for (int o = 0; o < RPT; o++) {
            const int orow = row0 + rbase + o;
            if (orow < OH) {
                u64 r;
                asm("add.rn.f32x2 %0, %1, %2;" : "=l"(r) : "l"(acc[o]), "l"(b2));
                *(u64*)&out[(size_t)orow * OW + ocol] = r;
            }
        }
    }
}

extern "C" void kernel_launch(void* const* d_in, const int* in_sizes, int n_in,
                              void* d_out, int out_size)
{
    const float* x    = (const float*)d_in[0];
    const float* wgt  = (const float*)d_in[1];
    const float* bias = (const float*)d_in[2];
    float* out        = (float*)d_out;

    dim3 block(TPB, 1, 1);
    dim3 grid((OW + TILE_X - 1) / TILE_X, (OH + TILE_Y - 1) / TILE_Y, 1);
    conv7x7_ev_kernel<<<grid, block>>>(x, wgt, bias, out);
}

// round 10
// speedup vs baseline: 1.0047x; 1.0047x over previous
#include <cuda_runtime.h>

#define H 8192
#define W 8192
#define KH 7
#define KW 7
#define OH (H - KH + 1)   // 8186
#define OW (W - KW + 1)   // 8186

#define TPB    128
#define RPT    12                    // rows per thread
#define TILE_X 64                    // 32 lanes * 2 cols (one f32x2 pair)
#define TILE_Y 48                    // 4 warps * 12 rows
#define SM_H   (TILE_Y + KH - 1)     // 54
#define SM_W   (TILE_X + KW - 1)     // 70
#define SP     72                    // smem pitch (floats)
#define VLEN   (RPT + KH - 1)        // 18

typedef unsigned long long u64;

__device__ __forceinline__ u64 fma2(u64 a, u64 b, u64 c) {
    u64 d;
    asm("fma.rn.f32x2 %0, %1, %2, %3;" : "=l"(d) : "l"(a), "l"(b), "l"(c));
    return d;
}
__device__ __forceinline__ u64 splat2(float w) {
    u64 d;
    asm("mov.b64 %0, {%1, %1};" : "=l"(d) : "f"(w));
    return d;
}
// {hi(a), lo(b)} — 2 register MOVs
__device__ __forceinline__ u64 crossing(u64 a, u64 b) {
    u64 r;
    asm("{\n\t.reg .b32 al, ah, bl, bh;\n\t"
        "mov.b64 {al, ah}, %1;\n\t"
        "mov.b64 {bl, bh}, %2;\n\t"
        "mov.b64 %0, {ah, bl};\n\t}"
        : "=l"(r) : "l"(a), "l"(b));
    return r;
}

__global__ __launch_bounds__(TPB)
void conv7x7_slide_kernel(const float* __restrict__ x,
                          const float* __restrict__ wgt,
                          const float* __restrict__ bias,
                          float* __restrict__ out)
{
    __shared__ __align__(16) float tile[SM_H * SP];
    __shared__ __align__(16) u64 wpair[KW * KH];   // [kc*7 + kr] = {w,w}

    const int tid  = threadIdx.x;
    const int col0 = blockIdx.x * TILE_X;
    const int row0 = blockIdx.y * TILE_Y;

    if (tid < KH * KW) {
        const int kc = tid / 7;
        const int kr = tid - kc * 7;
        wpair[tid] = splat2(wgt[kr * KW + kc]);
    }

    // ---- Tile fill: single copy, clamped; float2 fast path for interior ----
    if (row0 + SM_H <= H && col0 + SM_W <= W) {
        for (int idx = tid; idx < SM_H * 35; idx += TPB) {
            const int r  = idx / 35;
            const int c2 = idx - r * 35;
            const float2 v = __ldg((const float2*)&x[(size_t)(row0 + r) * W + col0 + 2 * c2]);
            *(float2*)&tile[r * SP + 2 * c2] = v;
        }
    } else {
        for (int idx = tid; idx < SM_H * SM_W; idx += TPB) {
            const int r = idx / SM_W;
            const int c = idx - r * SM_W;
            const int gr = min(row0 + r, H - 1);
            const int gc = min(col0 + c, W - 1);
            tile[r * SP + c] = __ldg(&x[(size_t)gr * W + gc]);
        }
    }
    __syncthreads();

    const int lane  = tid & 31;
    const int rbase = (tid >> 5) * RPT;       // 0,12,24,36
    const int cb    = lane * 2;               // 0..62 (u64-aligned)

    u64 acc[RPT];
#pragma unroll
    for (int o = 0; o < RPT; o++) acc[o] = 0ULL;

    const float* base = &tile[rbase * SP + cb];

    // ---- Step 0: kc=0, load window W (kept live, overwritten in place later) ----
    u64 Wv[VLEN];
    {
        u64 w0[KH];
#pragma unroll
        for (int kr = 0; kr < KH; kr++) w0[kr] = wpair[kr];          // kc=0
#pragma unroll
        for (int t = 0; t < VLEN; t++) {
            const u64 Wn = *(const u64*)(base + t * SP);
            Wv[t] = Wn;
#pragma unroll
            for (int kr = 0; kr < KH; kr++) {
                const int o = t - kr;
                if (o >= 0 && o < RPT) acc[o] = fma2(Wn, w0[kr], acc[o]);
            }
        }
    }

    // ---- Steps s=1..3: load window kc=2s; odd kc=2s-1 = crossing(old, new);
    //      old window element dies at its crossing -> in-place update ----
#pragma unroll
    for (int s = 1; s <= 3; s++) {
        u64 wo[KH], we[KH];
#pragma unroll
        for (int kr = 0; kr < KH; kr++) {
            wo[kr] = wpair[(2 * s - 1) * 7 + kr];
            we[kr] = wpair[(2 * s) * 7 + kr];
        }
#pragma unroll
        for (int t = 0; t < VLEN; t++) {
            const u64 Wn = *(const u64*)(base + t * SP + 2 * s);
            const u64 X  = crossing(Wv[t], Wn);   // cols {2s-1, 2s}
            Wv[t] = Wn;                           // in-place: old dead after crossing
#pragma unroll
            for (int kr = 0; kr < KH; kr++) {
                const int o = t - kr;             // compile-time per (t,kr)
                if (o >= 0 && o < RPT) {
                    u64 a = acc[o];
                    a = fma2(X,  wo[kr], a);
                    a = fma2(Wn, we[kr], a);
                    acc[o] = a;
                }
            }
        }
    }

    // ---- Epilogue: bias + STG.64 (OW even: pairs never straddle) ----
    const u64 b2 = splat2(__ldg(&bias[0]));
    const int ocol = col0 + cb;
    if (ocol < OW) {
#pragma unroll
        for (int o = 0; o < RPT; o++) {
            const int orow = row0 + rbase + o;
            if (orow < OH) {
                u64 r;
                asm("add.rn.f32x2 %0, %1, %2;" : "=l"(r) : "l"(acc[o]), "l"(b2));
                *(u64*)&out[(size_t)orow * OW + ocol] = r;
            }
        }
    }
}

extern "C" void kernel_launch(void* const* d_in, const int* in_sizes, int n_in,
                              void* d_out, int out_size)
{
    const float* x    = (const float*)d_in[0];
    const float* wgt  = (const float*)d_in[1];
    const float* bias = (const float*)d_in[2];
    float* out        = (float*)d_out;

    dim3 block(TPB, 1, 1);
    dim3 grid((OW + TILE_X - 1) / TILE_X, (OH + TILE_Y - 1) / TILE_Y, 1);
    conv7x7_slide_kernel<<<grid, block>>>(x, wgt, bias, out);
}

// round 11
// speedup vs baseline: 1.4375x; 1.4308x over previous
#include <cuda_runtime.h>

#define H 8192
#define W 8192
#define KH 7
#define KW 7
#define OH (H - KH + 1)   // 8186
#define OW (W - KW + 1)   // 8186

#define TPB    128
#define RPT    8                     // rows per thread
#define TILE_X 64                    // 32 lanes * 2 cols (one f32x2 pair)
#define TILE_Y 32                    // 4 warps * 8 rows
#define SM_H   (TILE_Y + KH - 1)     // 38
#define SM_W   (TILE_X + KW - 1)     // 70
#define SP     72                    // smem pitch (floats)
#define VLEN   (RPT + KH - 1)        // 14

typedef unsigned long long u64;

__device__ __forceinline__ u64 fma2(u64 a, u64 b, u64 c) {
    u64 d;
    asm("fma.rn.f32x2 %0, %1, %2, %3;" : "=l"(d) : "l"(a), "l"(b), "l"(c));
    return d;
}
__device__ __forceinline__ u64 splat2(float w) {
    u64 d;
    asm("mov.b64 %0, {%1, %1};" : "=l"(d) : "f"(w));
    return d;
}
// {hi(a), lo(b)} — 2 register MOVs
__device__ __forceinline__ u64 crossing(u64 a, u64 b) {
    u64 r;
    asm("{\n\t.reg .b32 al, ah, bl, bh;\n\t"
        "mov.b64 {al, ah}, %1;\n\t"
        "mov.b64 {bl, bh}, %2;\n\t"
        "mov.b64 %0, {ah, bl};\n\t}"
        : "=l"(r) : "l"(a), "l"(b));
    return r;
}

__global__ __launch_bounds__(TPB)
void conv7x7_ph_kernel(const float* __restrict__ x,
                       const float* __restrict__ wgt,
                       const float* __restrict__ bias,
                       float* __restrict__ out)
{
    __shared__ __align__(16) float tile[SM_H * SP];
    __shared__ __align__(16) u64 wpair[KW * KH];   // [kc*7 + kr] = {w,w}

    const int tid  = threadIdx.x;
    const int col0 = blockIdx.x * TILE_X;
    const int row0 = blockIdx.y * TILE_Y;

    if (tid < KH * KW) {
        const int kc = tid / 7;
        const int kr = tid - kc * 7;
        wpair[tid] = splat2(wgt[kr * KW + kc]);
    }

    // ---- Single-copy tile fill, clamped; float2 fast path for interior ----
    if (row0 + SM_H <= H && col0 + SM_W <= W) {
        for (int idx = tid; idx < SM_H * 35; idx += TPB) {
            const int r  = idx / 35;
            const int c2 = idx - r * 35;
            const float2 v = __ldg((const float2*)&x[(size_t)(row0 + r) * W + col0 + 2 * c2]);
            *(float2*)&tile[r * SP + 2 * c2] = v;
        }
    } else {
        for (int idx = tid; idx < SM_H * SM_W; idx += TPB) {
            const int r = idx / SM_W;
            const int c = idx - r * SM_W;
            const int gr = min(row0 + r, H - 1);
            const int gc = min(col0 + c, W - 1);
            tile[r * SP + c] = __ldg(&x[(size_t)gr * W + gc]);
        }
    }
    __syncthreads();

    const int lane  = tid & 31;
    const int rbase = (tid >> 5) * RPT;   // 0,8,16,24
    const int cb    = lane * 2;           // 0..62 (u64-aligned)

    u64 acc[RPT];
#pragma unroll
    for (int o = 0; o < RPT; o++) acc[o] = 0ULL;

    const float* base = &tile[rbase * SP + cb];

    u64 va[VLEN], vb[VLEN];
    u64 w[KH];                             // only ONE kc's weights live (proven)

    // apply direct window macro: acc[o] += v[t] * w[kr], o = t-kr
#define APPLY(V)                                                         \
    _Pragma("unroll")                                                    \
    for (int t = 0; t < VLEN; t++) {                                     \
        _Pragma("unroll")                                                \
        for (int kr = 0; kr < KH; kr++) {                                \
            const int o = t - kr;                                        \
            if (o >= 0 && o < RPT) acc[o] = fma2((V)[t], w[kr], acc[o]); \
        }                                                                \
    }
    // apply crossed window: X = {hi(A[t]), lo(B[t])}, consumed immediately
#define APPLY_X(A, B)                                                    \
    _Pragma("unroll")                                                    \
    for (int t = 0; t < VLEN; t++) {                                     \
        const u64 Xt = crossing((A)[t], (B)[t]);                         \
        _Pragma("unroll")                                                \
        for (int kr = 0; kr < KH; kr++) {                                \
            const int o = t - kr;                                        \
            if (o >= 0 && o < RPT) acc[o] = fma2(Xt, w[kr], acc[o]);     \
        }                                                                \
    }
#define LOADW(KC)                                                        \
    _Pragma("unroll")                                                    \
    for (int kr = 0; kr < KH; kr++) w[kr] = wpair[(KC) * 7 + kr];
#define LOADV(V, OFF)                                                    \
    _Pragma("unroll")                                                    \
    for (int t = 0; t < VLEN; t++) (V)[t] = *(const u64*)(base + t * SP + (OFF));

    // Phases: kc = 0,1,2,3,4,5,6 with ping-pong windows (<=2 live)
    LOADV(va, 0);
    LOADW(0);  APPLY(va);
    LOADV(vb, 2);
    LOADW(1);  APPLY_X(va, vb);       // va dies here
    LOADW(2);  APPLY(vb);
    LOADV(va, 4);
    LOADW(3);  APPLY_X(vb, va);       // vb dies here
    LOADW(4);  APPLY(va);
    LOADV(vb, 6);
    LOADW(5);  APPLY_X(va, vb);       // va dies here
    LOADW(6);  APPLY(vb);

#undef APPLY
#undef APPLY_X
#undef LOADW
#undef LOADV

    // ---- Epilogue: bias + STG.64 (OW even: pairs never straddle) ----
    const u64 b2 = splat2(__ldg(&bias[0]));
    const int ocol = col0 + cb;
    if (ocol < OW) {
#pragma unroll
        for (int o = 0; o < RPT; o++) {
            const int orow = row0 + rbase + o;
            if (orow < OH) {
                u64 r;
                asm("add.rn.f32x2 %0, %1, %2;" : "=l"(r) : "l"(acc[o]), "l"(b2));
                *(u64*)&out[(size_t)orow * OW + ocol] = r;
            }
        }
    }
}

extern "C" void kernel_launch(void* const* d_in, const int* in_sizes, int n_in,
                              void* d_out, int out_size)
{
    const float* x    = (const float*)d_in[0];
    const float* wgt  = (const float*)d_in[1];
    const float* bias = (const float*)d_in[2];
    float* out        = (float*)d_out;

    dim3 block(TPB, 1, 1);
    dim3 grid((OW + TILE_X - 1) / TILE_X, (OH + TILE_Y - 1) / TILE_Y, 1);
    conv7x7_ph_kernel<<<grid, block>>>(x, wgt, bias, out);
}